// round 4
// baseline (speedup 1.0000x reference)
#include <cuda_runtime.h>
#include <cuda_bf16.h>
#include <cstdint>
#include <math.h>

// Problem dims
#define NTOK 32768
#define NEMB 4096
#define DIM  256

// Output layout (float32, concatenated in reference return order)
#define Q_OFF    ((size_t)0)
#define PERP_OFF ((size_t)8388608)
#define ENC_OFF  ((size_t)8388609)
#define IDX_OFF  ((size_t)142606337)
#define LOSS_OFF ((size_t)142639105)

// Scratch (device globals — no allocation allowed)
__device__ __nv_bfloat16 g_Wb[NEMB * DIM];
__device__ float  g_se[NEMB];
__device__ int    g_cand[NTOK * 8];
__device__ int    g_idx[NTOK];
__device__ int    g_hist[NEMB];
__device__ double g_part[8192];

// ---------------- helpers ----------------
__device__ __forceinline__ uint32_t smem_u32(const void* p) {
    uint32_t a;
    asm("{ .reg .u64 t; cvta.to.shared.u64 t, %1; cvt.u32.u64 %0, t; }"
        : "=r"(a) : "l"(p));
    return a;
}

__device__ __forceinline__ uint4 pack8(float4 a, float4 b) {
    __nv_bfloat162 p0 = __floats2bfloat162_rn(a.x, a.y);
    __nv_bfloat162 p1 = __floats2bfloat162_rn(a.z, a.w);
    __nv_bfloat162 p2 = __floats2bfloat162_rn(b.x, b.y);
    __nv_bfloat162 p3 = __floats2bfloat162_rn(b.z, b.w);
    uint4 v;
    v.x = *reinterpret_cast<uint32_t*>(&p0);
    v.y = *reinterpret_cast<uint32_t*>(&p1);
    v.z = *reinterpret_cast<uint32_t*>(&p2);
    v.w = *reinterpret_cast<uint32_t*>(&p3);
    return v;
}

__device__ __forceinline__ void ldsm_x4(uint32_t& r0, uint32_t& r1,
                                        uint32_t& r2, uint32_t& r3, uint32_t a) {
    asm volatile("ldmatrix.sync.aligned.m8n8.x4.shared.b16 {%0,%1,%2,%3}, [%4];"
                 : "=r"(r0), "=r"(r1), "=r"(r2), "=r"(r3) : "r"(a));
}

__device__ __forceinline__ void mma16816(float& c0, float& c1, float& c2, float& c3,
                                         uint32_t a0, uint32_t a1, uint32_t a2, uint32_t a3,
                                         uint32_t b0, uint32_t b1) {
    asm volatile(
        "mma.sync.aligned.m16n8k16.row.col.f32.bf16.bf16.f32 "
        "{%0,%1,%2,%3}, {%4,%5,%6,%7}, {%8,%9}, {%0,%1,%2,%3};"
        : "+f"(c0), "+f"(c1), "+f"(c2), "+f"(c3)
        : "r"(a0), "r"(a1), "r"(a2), "r"(a3), "r"(b0), "r"(b1));
}

// ---------------- K1: prep W (bf16 copy + ||e||^2 + hist zero) ----------------
__global__ __launch_bounds__(256) void k_prep(const float* __restrict__ W) {
    int lane = threadIdx.x & 31;
    int wr = blockIdx.x * 8 + (threadIdx.x >> 5);
    const float4* p = (const float4*)(W + (size_t)wr * DIM);
    float4 a = p[2 * lane], b = p[2 * lane + 1];
    ((uint4*)g_Wb)[(size_t)wr * 32 + lane] = pack8(a, b);
    double s = (double)a.x * a.x + (double)a.y * a.y + (double)a.z * a.z + (double)a.w * a.w
             + (double)b.x * b.x + (double)b.y * b.y + (double)b.z * b.z + (double)b.w * b.w;
    #pragma unroll
    for (int o = 16; o; o >>= 1) s += __shfl_xor_sync(0xffffffffu, s, o);
    if (lane == 0) g_se[wr] = (float)s;
    int gid = blockIdx.x * 256 + threadIdx.x;
    if (gid < NEMB) g_hist[gid] = 0;
}

// ---------------- K2: bf16 mma.sync GEMM + fused per-row top-8 ----------------
// 256 CTAs x 256 threads. Per CTA: 128 token rows; 32 chunks of 128 codes; K=256.
// smem: A (128 x 264 bf16, 528B rows), B (same), D (128 x 132 f32, 528B rows).
#define ROWB 528            // padded row stride bytes (132 words; mod 32 banks = 4)
#define AOFF 0
#define BOFF 67584
#define DOFF 135168
#define SMEM_TOTAL 202752

__global__ __launch_bounds__(256, 1) void k_gemm(const float* __restrict__ X) {
    extern __shared__ char smem[];
    uint32_t sb = smem_u32(smem);
    const int tid = threadIdx.x, wid = tid >> 5, lane = tid & 31;
    const int mh = wid >> 2;          // 0..1 : which 64-row half
    const int nq = wid & 3;           // 0..3 : which 32-col quarter

    const int row0 = blockIdx.x * 128;
    // Load + convert A tile (128 rows x 256 f32 -> bf16, padded rows)
    #pragma unroll
    for (int i = 0; i < 16; i++) {
        int t = tid + i * 256;
        int r = t >> 5, k8 = t & 31;
        const float4* p = (const float4*)(X + (size_t)(row0 + r) * DIM + k8 * 8);
        float4 a = p[0], b = p[1];
        *(uint4*)(smem + AOFF + r * ROWB + k8 * 16) = pack8(a, b);
    }

    // ldmatrix lane addressing (computed once)
    const int ag = lane >> 3;                     // matrix id group
    const int a_r = (lane & 7) + (ag & 1) * 8;    // A: row within m16 tile
    const int a_k = (ag >> 1) * 8;                // A: k offset within k16
    const int b_n = (lane & 7) + (ag >> 1) * 8;   // B: code row within n16
    const int b_k = (ag & 1) * 8;                 // B: k offset within k16

    float tv[8]; int tj[8];
    #pragma unroll
    for (int s = 0; s < 8; s++) { tv[s] = -3.4e38f; tj[s] = 0; }
    float thr = -3.4e38f; int slot = 0;

    const uint4* wb = (const uint4*)g_Wb;
    for (int c = 0; c < 32; c++) {
        // load B chunk: 128 codes x 256 bf16 (already bf16 in g_Wb)
        #pragma unroll
        for (int i = 0; i < 16; i++) {
            int t = tid + i * 256;
            int r = t >> 5, c16 = t & 31;
            uint4 v = wb[((size_t)(c * 128 + r)) * 32 + c16];
            *(uint4*)(smem + BOFF + r * ROWB + c16 * 16) = v;
        }
        __syncthreads();

        float acc[4][4][4];
        #pragma unroll
        for (int mt = 0; mt < 4; mt++)
            #pragma unroll
            for (int nt = 0; nt < 4; nt++)
                #pragma unroll
                for (int q = 0; q < 4; q++) acc[mt][nt][q] = 0.0f;

        #pragma unroll
        for (int kk = 0; kk < 16; kk++) {
            const int k0 = kk * 16;
            uint32_t af[4][4];
            #pragma unroll
            for (int mt = 0; mt < 4; mt++) {
                uint32_t addr = sb + AOFF + (mh * 64 + mt * 16 + a_r) * ROWB + (k0 + a_k) * 2;
                ldsm_x4(af[mt][0], af[mt][1], af[mt][2], af[mt][3], addr);
            }
            uint32_t bf[2][4];
            #pragma unroll
            for (int nt2 = 0; nt2 < 2; nt2++) {
                uint32_t addr = sb + BOFF + (nq * 32 + nt2 * 16 + b_n) * ROWB + (k0 + b_k) * 2;
                ldsm_x4(bf[nt2][0], bf[nt2][1], bf[nt2][2], bf[nt2][3], addr);
            }
            #pragma unroll
            for (int mt = 0; mt < 4; mt++)
                #pragma unroll
                for (int nt = 0; nt < 4; nt++) {
                    uint32_t b0 = bf[nt >> 1][(nt & 1) * 2];
                    uint32_t b1 = bf[nt >> 1][(nt & 1) * 2 + 1];
                    mma16816(acc[mt][nt][0], acc[mt][nt][1], acc[mt][nt][2], acc[mt][nt][3],
                             af[mt][0], af[mt][1], af[mt][2], af[mt][3], b0, b1);
                }
        }

        // store D fragments to smem
        #pragma unroll
        for (int mt = 0; mt < 4; mt++) {
            int r = mh * 64 + mt * 16 + (lane >> 2);
            #pragma unroll
            for (int nt = 0; nt < 4; nt++) {
                int cb = nq * 32 + nt * 8 + 2 * (lane & 3);
                *(float2*)(smem + DOFF + r * ROWB + cb * 4) =
                    make_float2(acc[mt][nt][0], acc[mt][nt][1]);
                *(float2*)(smem + DOFF + (r + 8) * ROWB + cb * 4) =
                    make_float2(acc[mt][nt][2], acc[mt][nt][3]);
            }
        }
        __syncthreads();

        // per-row top-8 scan: thread tid (<128) owns row tid
        if (tid < 128) {
            const float4* drow = (const float4*)(smem + DOFF + tid * ROWB);
            int jb = c * 128;
            #pragma unroll 8
            for (int q = 0; q < 32; q++) {
                float4 v4 = drow[q];
                #pragma unroll
                for (int e = 0; e < 4; e++) {
                    float v = (e == 0) ? v4.x : (e == 1) ? v4.y : (e == 2) ? v4.z : v4.w;
                    if (v > thr) {
                        int j = jb + q * 4 + e;
                        #pragma unroll
                        for (int s = 0; s < 8; s++)
                            if (s == slot) { tv[s] = v; tj[s] = j; }
                        thr = tv[0]; slot = 0;
                        #pragma unroll
                        for (int s = 1; s < 8; s++)
                            if (tv[s] < thr) { thr = tv[s]; slot = s; }
                    }
                }
            }
        }
        __syncthreads();   // D consumed before next chunk's store; B free for reload
    }
    if (tid < 128) {
        int row = row0 + tid;
        #pragma unroll
        for (int s = 0; s < 8; s++) g_cand[row * 8 + s] = tj[s];
    }
}

// ---------------- K3: exact refine of 8 candidates per row ----------------
__global__ __launch_bounds__(256) void k_refine(const float* __restrict__ X,
                                                const float* __restrict__ W,
                                                float* __restrict__ oidx) {
    int lane = threadIdx.x & 31;
    int row = blockIdx.x * 8 + (threadIdx.x >> 5);
    const float4* xr = (const float4*)(X + (size_t)row * DIM);
    float4 xa = xr[2 * lane], xb = xr[2 * lane + 1];

    double sx = (double)xa.x * xa.x + (double)xa.y * xa.y + (double)xa.z * xa.z + (double)xa.w * xa.w
              + (double)xb.x * xb.x + (double)xb.y * xb.y + (double)xb.z * xb.z + (double)xb.w * xb.w;
    #pragma unroll
    for (int o = 16; o; o >>= 1) sx += __shfl_xor_sync(0xffffffffu, sx, o);
    float sxf = (float)sx;

    float bd = 3.4e38f; int bj = 1 << 30;
    #pragma unroll
    for (int s = 0; s < 8; s++) {
        int j = g_cand[row * 8 + s];
        const float4* wr = (const float4*)(W + (size_t)j * DIM);
        float4 wa = wr[2 * lane], wv = wr[2 * lane + 1];
        double m = (double)xa.x * wa.x + (double)xa.y * wa.y + (double)xa.z * wa.z + (double)xa.w * wa.w
                 + (double)xb.x * wv.x + (double)xb.y * wv.y + (double)xb.z * wv.z + (double)xb.w * wv.w;
        #pragma unroll
        for (int o = 16; o; o >>= 1) m += __shfl_xor_sync(0xffffffffu, m, o);
        float mf = (float)m;                        // ~= reference's fp32 matmul entry
        float t1 = __fadd_rn(sxf, g_se[j]);         // fl(s_x + s_e[j])
        float d  = __fsub_rn(t1, 2.0f * mf);        // fl(t1 - 2m)  (x2 exact)
        if (d < bd || (d == bd && j < bj)) { bd = d; bj = j; }
    }
    if (lane == 0) {
        g_idx[row] = bj;
        oidx[row] = (float)bj;
        atomicAdd(&g_hist[bj], 1);
    }
}

// ---------------- K4: quantized_st + squared-diff partials ----------------
__global__ __launch_bounds__(256) void k_quant(const float* __restrict__ X,
                                               const float* __restrict__ W,
                                               float* __restrict__ oq) {
    __shared__ double sred[256];
    size_t base = (size_t)blockIdx.x * 1024 + threadIdx.x * 4;
    int row = (int)(base >> 8);
    int k = (int)(base & 255);
    int j = g_idx[row];
    float4 x = *(const float4*)(X + base);
    float4 w = *(const float4*)(W + (size_t)j * DIM + k);
    float d0 = __fsub_rn(w.x, x.x), d1 = __fsub_rn(w.y, x.y);
    float d2 = __fsub_rn(w.z, x.z), d3 = __fsub_rn(w.w, x.w);
    float4 r;
    r.x = __fadd_rn(x.x, d0); r.y = __fadd_rn(x.y, d1);
    r.z = __fadd_rn(x.z, d2); r.w = __fadd_rn(x.w, d3);
    *(float4*)(oq + base) = r;
    sred[threadIdx.x] = (double)d0 * d0 + (double)d1 * d1 + (double)d2 * d2 + (double)d3 * d3;
    __syncthreads();
    for (int o = 128; o; o >>= 1) {
        if (threadIdx.x < o) sred[threadIdx.x] += sred[threadIdx.x + o];
        __syncthreads();
    }
    if (threadIdx.x == 0) g_part[blockIdx.x] = sred[0];
}

// ---------------- K5: loss + perplexity ----------------
__global__ __launch_bounds__(1024) void k_final(float* __restrict__ out) {
    __shared__ double sA[1024], sB[1024];
    int t = threadIdx.x;
    double a = 0.0;
    for (int i = t; i < 8192; i += 1024) a += g_part[i];
    double b = 0.0;
    for (int i = t; i < 4096; i += 1024) {
        float p = (float)g_hist[i] / 32768.0f;
        b += (double)(p * logf(p + 1e-10f));
    }
    sA[t] = a; sB[t] = b; __syncthreads();
    for (int o = 512; o; o >>= 1) {
        if (t < o) { sA[t] += sA[t + o]; sB[t] += sB[t + o]; }
        __syncthreads();
    }
    if (t == 0) {
        double mse = sA[0] / 8388608.0;
        float c = (float)mse;
        out[LOSS_OFF] = __fadd_rn(c, 0.25f * c);   // codebook + 0.25*commitment (equal values)
        out[PERP_OFF] = expf(-(float)sB[0]);
    }
}

// ---------------- K6: scatter one-hot ones ----------------
__global__ __launch_bounds__(256) void k_scatter(float* __restrict__ enc) {
    int row = blockIdx.x * 256 + threadIdx.x;
    enc[(size_t)row * NEMB + g_idx[row]] = 1.0f;
}

// ---------------- launch ----------------
extern "C" void kernel_launch(void* const* d_in, const int* in_sizes, int n_in,
                              void* d_out, int out_size) {
    const float* X = (const float*)d_in[0];
    const float* W = (const float*)d_in[1];
    float* out = (float*)d_out;

    cudaFuncSetAttribute(k_gemm, cudaFuncAttributeMaxDynamicSharedMemorySize, SMEM_TOTAL);

    k_prep<<<512, 256>>>(W);
    cudaMemsetAsync(out + ENC_OFF, 0, (size_t)NTOK * NEMB * sizeof(float));
    k_gemm<<<256, 256, SMEM_TOTAL>>>(X);
    k_refine<<<4096, 256>>>(X, W, out + IDX_OFF);
    k_quant<<<8192, 256>>>(X, W, out);
    k_final<<<1, 1024>>>(out);
    k_scatter<<<128, 256>>>(out + ENC_OFF);
}

// round 5
// speedup vs baseline: 1.2505x; 1.2505x over previous
#include <cuda_runtime.h>
#include <cuda_bf16.h>
#include <cstdint>
#include <math.h>

// Problem dims
#define NTOK 32768
#define NEMB 4096
#define DIM  256
#define NCAND 6

// Output layout (float32, concatenated in reference return order)
#define Q_OFF    ((size_t)0)
#define PERP_OFF ((size_t)8388608)
#define ENC_OFF  ((size_t)8388609)
#define IDX_OFF  ((size_t)142606337)
#define LOSS_OFF ((size_t)142639105)

// Scratch (device globals — no allocation allowed)
__device__ __nv_bfloat16 g_Wb[NEMB * DIM];
__device__ float  g_se[NEMB];
__device__ int    g_cand[NTOK * NCAND];
__device__ int    g_idx[NTOK];
__device__ int    g_hist[NEMB];
__device__ double g_mse;

// ---------------- helpers ----------------
__device__ __forceinline__ uint32_t smem_u32(const void* p) {
    uint32_t a;
    asm("{ .reg .u64 t; cvta.to.shared.u64 t, %1; cvt.u32.u64 %0, t; }"
        : "=r"(a) : "l"(p));
    return a;
}

__device__ __forceinline__ uint4 pack8(float4 a, float4 b) {
    __nv_bfloat162 p0 = __floats2bfloat162_rn(a.x, a.y);
    __nv_bfloat162 p1 = __floats2bfloat162_rn(a.z, a.w);
    __nv_bfloat162 p2 = __floats2bfloat162_rn(b.x, b.y);
    __nv_bfloat162 p3 = __floats2bfloat162_rn(b.z, b.w);
    uint4 v;
    v.x = *reinterpret_cast<uint32_t*>(&p0);
    v.y = *reinterpret_cast<uint32_t*>(&p1);
    v.z = *reinterpret_cast<uint32_t*>(&p2);
    v.w = *reinterpret_cast<uint32_t*>(&p3);
    return v;
}

__device__ __forceinline__ void ldsm_x4(uint32_t& r0, uint32_t& r1,
                                        uint32_t& r2, uint32_t& r3, uint32_t a) {
    asm volatile("ldmatrix.sync.aligned.m8n8.x4.shared.b16 {%0,%1,%2,%3}, [%4];"
                 : "=r"(r0), "=r"(r1), "=r"(r2), "=r"(r3) : "r"(a));
}

__device__ __forceinline__ void mma16816(float& c0, float& c1, float& c2, float& c3,
                                         uint32_t a0, uint32_t a1, uint32_t a2, uint32_t a3,
                                         uint32_t b0, uint32_t b1) {
    asm volatile(
        "mma.sync.aligned.m16n8k16.row.col.f32.bf16.bf16.f32 "
        "{%0,%1,%2,%3}, {%4,%5,%6,%7}, {%8,%9}, {%0,%1,%2,%3};"
        : "+f"(c0), "+f"(c1), "+f"(c2), "+f"(c3)
        : "r"(a0), "r"(a1), "r"(a2), "r"(a3), "r"(b0), "r"(b1));
}

__device__ __forceinline__ void cp_async16(uint32_t sdst, const void* gsrc) {
    asm volatile(
        "{ .reg .u64 g; cvta.to.global.u64 g, %1; "
        "cp.async.cg.shared.global [%0], [g], 16; }"
        :: "r"(sdst), "l"(gsrc) : "memory");
}
#define CP_COMMIT() asm volatile("cp.async.commit_group;" ::: "memory")
#define CP_WAIT0()  asm volatile("cp.async.wait_group 0;" ::: "memory")

// ---------------- K1: prep W (bf16 copy + ||e||^2) ----------------
__global__ __launch_bounds__(256) void k_prep(const float* __restrict__ W) {
    int lane = threadIdx.x & 31;
    int wr = blockIdx.x * 8 + (threadIdx.x >> 5);
    const float4* p = (const float4*)(W + (size_t)wr * DIM);
    float4 a = p[2 * lane], b = p[2 * lane + 1];
    ((uint4*)g_Wb)[(size_t)wr * 32 + lane] = pack8(a, b);
    double s = (double)a.x * a.x + (double)a.y * a.y + (double)a.z * a.z + (double)a.w * a.w
             + (double)b.x * b.x + (double)b.y * b.y + (double)b.z * b.z + (double)b.w * b.w;
    #pragma unroll
    for (int o = 16; o; o >>= 1) s += __shfl_xor_sync(0xffffffffu, s, o);
    if (lane == 0) g_se[wr] = (float)s;
}

// ---------------- K1b: zero hist (+mse); also launch-count padding ----------------
__global__ __launch_bounds__(256) void k_hist0(int half) {
    int gid = half * 2048 + blockIdx.x * 256 + threadIdx.x;
    g_hist[gid] = 0;
    if (gid == 0) g_mse = 0.0;
}

// ---------------- K2: pipelined bf16 mma.sync GEMM + fused per-row top-6 ----------------
// 256 CTAs x 256 threads. Per CTA: 128 token rows; 32 chunks of 128 codes; K=256.
// smem: A (128 x 528B), B0/B1 double buffer (128 x 528B each); D reuses consumed B buf.
#define ROWB 528
#define AOFF 0
#define B0OFF 67584
#define B1OFF 135168
#define SMEM_TOTAL 202752

__global__ __launch_bounds__(256, 1) void k_gemm(const float* __restrict__ X) {
    extern __shared__ char smem[];
    uint32_t sb = smem_u32(smem);
    const int tid = threadIdx.x, lane = tid & 31, wid = tid >> 5;
    const int mh = wid >> 2;          // 0..1 : 64-row half
    const int nq = wid & 3;           // 0..3 : 32-col quarter

    // Preload B chunk 0 (cp.async, overlaps A conversion below)
    const char* wb = (const char*)g_Wb;
    {
        #pragma unroll
        for (int i = 0; i < 16; i++) {
            int t = tid + i * 256;
            int r = t >> 5, c16 = t & 31;
            cp_async16(sb + B0OFF + r * ROWB + c16 * 16,
                       wb + (size_t)r * 512 + c16 * 16);
        }
        CP_COMMIT();
    }

    const int row0 = blockIdx.x * 128;
    // Load + convert A tile (128 rows x 256 f32 -> bf16, padded rows)
    #pragma unroll
    for (int i = 0; i < 16; i++) {
        int t = tid + i * 256;
        int r = t >> 5, k8 = t & 31;
        const float4* p = (const float4*)(X + (size_t)(row0 + r) * DIM + k8 * 8);
        float4 a = p[0], b = p[1];
        *(uint4*)(smem + AOFF + r * ROWB + k8 * 16) = pack8(a, b);
    }

    // ldmatrix lane addressing
    const int ag = lane >> 3;
    const int a_r = (lane & 7) + (ag & 1) * 8;
    const int a_k = (ag >> 1) * 8;
    const int b_n = (lane & 7) + (ag >> 1) * 8;
    const int b_k = (ag & 1) * 8;

    float tv[NCAND]; int tj[NCAND];
    #pragma unroll
    for (int s = 0; s < NCAND; s++) { tv[s] = -3.4e38f; tj[s] = 0; }
    float thr = -3.4e38f; int slot = 0;

    for (int c = 0; c < 32; c++) {
        const uint32_t buf = (c & 1) ? B1OFF : B0OFF;
        const uint32_t nbuf = (c & 1) ? B0OFF : B1OFF;

        CP_WAIT0();
        __syncthreads();          // chunk c's B tile visible to all warps

        // Kick off loads for chunk c+1 into the other buffer (overlaps MMA+scan)
        if (c + 1 < 32) {
            #pragma unroll
            for (int i = 0; i < 16; i++) {
                int t = tid + i * 256;
                int r = t >> 5, c16 = t & 31;
                cp_async16(sb + nbuf + r * ROWB + c16 * 16,
                           wb + ((size_t)(c + 1) * 128 + r) * 512 + c16 * 16);
            }
            CP_COMMIT();
        }

        float acc[4][4][4];
        #pragma unroll
        for (int mt = 0; mt < 4; mt++)
            #pragma unroll
            for (int nt = 0; nt < 4; nt++)
                #pragma unroll
                for (int q = 0; q < 4; q++) acc[mt][nt][q] = 0.0f;

        #pragma unroll
        for (int kk = 0; kk < 16; kk++) {
            const int k0 = kk * 16;
            uint32_t af[4][4];
            #pragma unroll
            for (int mt = 0; mt < 4; mt++) {
                uint32_t addr = sb + AOFF + (mh * 64 + mt * 16 + a_r) * ROWB + (k0 + a_k) * 2;
                ldsm_x4(af[mt][0], af[mt][1], af[mt][2], af[mt][3], addr);
            }
            uint32_t bf[2][4];
            #pragma unroll
            for (int nt2 = 0; nt2 < 2; nt2++) {
                uint32_t addr = sb + buf + (nq * 32 + nt2 * 16 + b_n) * ROWB + (k0 + b_k) * 2;
                ldsm_x4(bf[nt2][0], bf[nt2][1], bf[nt2][2], bf[nt2][3], addr);
            }
            #pragma unroll
            for (int mt = 0; mt < 4; mt++)
                #pragma unroll
                for (int nt = 0; nt < 4; nt++) {
                    uint32_t b0 = bf[nt >> 1][(nt & 1) * 2];
                    uint32_t b1 = bf[nt >> 1][(nt & 1) * 2 + 1];
                    mma16816(acc[mt][nt][0], acc[mt][nt][1], acc[mt][nt][2], acc[mt][nt][3],
                             af[mt][0], af[mt][1], af[mt][2], af[mt][3], b0, b1);
                }
        }
        __syncthreads();          // all warps done reading buf; safe to overwrite with D

        // store D fragments into the consumed B buffer
        #pragma unroll
        for (int mt = 0; mt < 4; mt++) {
            int r = mh * 64 + mt * 16 + (lane >> 2);
            #pragma unroll
            for (int nt = 0; nt < 4; nt++) {
                int cb = nq * 32 + nt * 8 + 2 * (lane & 3);
                *(float2*)(smem + buf + r * ROWB + cb * 4) =
                    make_float2(acc[mt][nt][0], acc[mt][nt][1]);
                *(float2*)(smem + buf + (r + 8) * ROWB + cb * 4) =
                    make_float2(acc[mt][nt][2], acc[mt][nt][3]);
            }
        }
        __syncthreads();

        // per-row top-6 scan: thread tid (<128) owns row tid
        if (tid < 128) {
            const float4* drow = (const float4*)(smem + buf + tid * ROWB);
            int jb = c * 128;
            #pragma unroll 8
            for (int q = 0; q < 32; q++) {
                float4 v4 = drow[q];
                #pragma unroll
                for (int e = 0; e < 4; e++) {
                    float v = (e == 0) ? v4.x : (e == 1) ? v4.y : (e == 2) ? v4.z : v4.w;
                    if (v > thr) {
                        int j = jb + q * 4 + e;
                        #pragma unroll
                        for (int s = 0; s < NCAND; s++)
                            if (s == slot) { tv[s] = v; tj[s] = j; }
                        thr = tv[0]; slot = 0;
                        #pragma unroll
                        for (int s = 1; s < NCAND; s++)
                            if (tv[s] < thr) { thr = tv[s]; slot = s; }
                    }
                }
            }
        }
        // note: next iteration's CP_WAIT0+__syncthreads fences the scan before
        // this buffer is refilled two chunks later.
    }
    if (tid < 128) {
        int row = row0 + tid;
        #pragma unroll
        for (int s = 0; s < NCAND; s++) g_cand[row * NCAND + s] = tj[s];
    }
}

// ---------------- K3: exact refine + quantized_st + losses + scatter ----------------
// One warp per row; 8 rows per block.
__global__ __launch_bounds__(256) void k_refine(const float* __restrict__ X,
                                                const float* __restrict__ W,
                                                float* __restrict__ out) {
    __shared__ double sred[8];
    int lane = threadIdx.x & 31;
    int wip = threadIdx.x >> 5;
    int row = blockIdx.x * 8 + wip;
    const float4* xr = (const float4*)(X + (size_t)row * DIM);
    float4 xa = xr[2 * lane], xb = xr[2 * lane + 1];

    double sx = (double)xa.x * xa.x + (double)xa.y * xa.y + (double)xa.z * xa.z + (double)xa.w * xa.w
              + (double)xb.x * xb.x + (double)xb.y * xb.y + (double)xb.z * xb.z + (double)xb.w * xb.w;
    #pragma unroll
    for (int o = 16; o; o >>= 1) sx += __shfl_xor_sync(0xffffffffu, sx, o);
    float sxf = (float)sx;

    float bd = 3.4e38f; int bj = 1 << 30;
    #pragma unroll
    for (int s = 0; s < NCAND; s++) {
        int j = g_cand[row * NCAND + s];
        const float4* wr = (const float4*)(W + (size_t)j * DIM);
        float4 wa = wr[2 * lane], wv = wr[2 * lane + 1];
        double m = (double)xa.x * wa.x + (double)xa.y * wa.y + (double)xa.z * wa.z + (double)xa.w * wa.w
                 + (double)xb.x * wv.x + (double)xb.y * wv.y + (double)xb.z * wv.z + (double)xb.w * wv.w;
        #pragma unroll
        for (int o = 16; o; o >>= 1) m += __shfl_xor_sync(0xffffffffu, m, o);
        float mf = (float)m;                        // ~= reference's fp32 matmul entry
        float t1 = __fadd_rn(sxf, g_se[j]);         // fl(s_x + s_e[j])
        float d  = __fsub_rn(t1, 2.0f * mf);        // fl(t1 - 2m)  (x2 exact)
        if (d < bd || (d == bd && j < bj)) { bd = d; bj = j; }
    }

    // winner row reload (L2-hot) -> quantized_st + diff partials
    const float4* wr = (const float4*)(W + (size_t)bj * DIM);
    float4 wa = wr[2 * lane], wv = wr[2 * lane + 1];
    float d0 = __fsub_rn(wa.x, xa.x), d1 = __fsub_rn(wa.y, xa.y);
    float d2 = __fsub_rn(wa.z, xa.z), d3 = __fsub_rn(wa.w, xa.w);
    float d4 = __fsub_rn(wv.x, xb.x), d5 = __fsub_rn(wv.y, xb.y);
    float d6 = __fsub_rn(wv.z, xb.z), d7 = __fsub_rn(wv.w, xb.w);
    float4 qa, qb;
    qa.x = __fadd_rn(xa.x, d0); qa.y = __fadd_rn(xa.y, d1);
    qa.z = __fadd_rn(xa.z, d2); qa.w = __fadd_rn(xa.w, d3);
    qb.x = __fadd_rn(xb.x, d4); qb.y = __fadd_rn(xb.y, d5);
    qb.z = __fadd_rn(xb.z, d6); qb.w = __fadd_rn(xb.w, d7);
    float4* oq = (float4*)(out + Q_OFF + (size_t)row * DIM);
    oq[2 * lane] = qa; oq[2 * lane + 1] = qb;

    double ds = (double)d0 * d0 + (double)d1 * d1 + (double)d2 * d2 + (double)d3 * d3
              + (double)d4 * d4 + (double)d5 * d5 + (double)d6 * d6 + (double)d7 * d7;
    #pragma unroll
    for (int o = 16; o; o >>= 1) ds += __shfl_xor_sync(0xffffffffu, ds, o);
    if (lane == 0) {
        sred[wip] = ds;
        g_idx[row] = bj;
        out[IDX_OFF + row] = (float)bj;
        out[ENC_OFF + (size_t)row * NEMB + bj] = 1.0f;   // scatter one-hot
        atomicAdd(&g_hist[bj], 1);
    }
    __syncthreads();
    if (threadIdx.x == 0) {
        double t = 0.0;
        #pragma unroll
        for (int i = 0; i < 8; i++) t += sred[i];
        atomicAdd(&g_mse, t);
    }
}

// ---------------- K5: loss + perplexity ----------------
__global__ __launch_bounds__(1024) void k_final(float* __restrict__ out) {
    __shared__ double sB[1024];
    int t = threadIdx.x;
    double b = 0.0;
    for (int i = t; i < 4096; i += 1024) {
        float p = (float)g_hist[i] / 32768.0f;
        b += (double)(p * logf(p + 1e-10f));
    }
    sB[t] = b; __syncthreads();
    for (int o = 512; o; o >>= 1) {
        if (t < o) sB[t] += sB[t + o];
        __syncthreads();
    }
    if (t == 0) {
        double mse = g_mse / 8388608.0;
        float c = (float)mse;
        out[LOSS_OFF] = __fadd_rn(c, 0.25f * c);   // codebook + 0.25*commitment (equal values)
        out[PERP_OFF] = expf(-(float)sB[0]);
    }
}

// ---------------- launch ----------------
extern "C" void kernel_launch(void* const* d_in, const int* in_sizes, int n_in,
                              void* d_out, int out_size) {
    const float* X = (const float*)d_in[0];
    const float* W = (const float*)d_in[1];
    float* out = (float*)d_out;

    cudaFuncSetAttribute(k_gemm, cudaFuncAttributeMaxDynamicSharedMemorySize, SMEM_TOTAL);

    k_prep<<<512, 256>>>(W);                                            // launch 1
    cudaMemsetAsync(out + ENC_OFF, 0, (size_t)NTOK * NEMB * sizeof(float)); // 2
    k_hist0<<<8, 256>>>(0);                                             // 3
    k_hist0<<<8, 256>>>(1);                                             // 4
    k_gemm<<<256, 256, SMEM_TOTAL>>>(X);                                // 5 <- ncu slot
    k_refine<<<4096, 256>>>(X, W, out);                                 // 6
    k_final<<<1, 1024>>>(out);                                          // 7
}

// round 6
// speedup vs baseline: 1.7991x; 1.4387x over previous
#include <cuda_runtime.h>
#include <cuda_bf16.h>
#include <cstdint>
#include <math.h>

// Problem dims
#define NTOK 32768
#define NEMB 4096
#define DIM  256
#define NCAND 6

// Output layout (float32, concatenated in reference return order)
#define Q_OFF    ((size_t)0)
#define PERP_OFF ((size_t)8388608)
#define ENC_OFF  ((size_t)8388609)
#define IDX_OFF  ((size_t)142606337)
#define LOSS_OFF ((size_t)142639105)

// Scratch (device globals — no allocation allowed)
__device__ __nv_bfloat16 g_Wb[NEMB * DIM];
__device__ float  g_se[NEMB];
__device__ int    g_cand[NTOK * NCAND];
__device__ int    g_idx[NTOK];
__device__ int    g_hist[NEMB];
__device__ double g_mse;

// ---------------- helpers ----------------
__device__ __forceinline__ uint32_t smem_u32(const void* p) {
    uint32_t a;
    asm("{ .reg .u64 t; cvta.to.shared.u64 t, %1; cvt.u32.u64 %0, t; }"
        : "=r"(a) : "l"(p));
    return a;
}

__device__ __forceinline__ uint4 pack8(float4 a, float4 b) {
    __nv_bfloat162 p0 = __floats2bfloat162_rn(a.x, a.y);
    __nv_bfloat162 p1 = __floats2bfloat162_rn(a.z, a.w);
    __nv_bfloat162 p2 = __floats2bfloat162_rn(b.x, b.y);
    __nv_bfloat162 p3 = __floats2bfloat162_rn(b.z, b.w);
    uint4 v;
    v.x = *reinterpret_cast<uint32_t*>(&p0);
    v.y = *reinterpret_cast<uint32_t*>(&p1);
    v.z = *reinterpret_cast<uint32_t*>(&p2);
    v.w = *reinterpret_cast<uint32_t*>(&p3);
    return v;
}

__device__ __forceinline__ void ldsm_x4(uint32_t& r0, uint32_t& r1,
                                        uint32_t& r2, uint32_t& r3, uint32_t a) {
    asm volatile("ldmatrix.sync.aligned.m8n8.x4.shared.b16 {%0,%1,%2,%3}, [%4];"
                 : "=r"(r0), "=r"(r1), "=r"(r2), "=r"(r3) : "r"(a));
}

__device__ __forceinline__ void mma16816(float& c0, float& c1, float& c2, float& c3,
                                         uint32_t a0, uint32_t a1, uint32_t a2, uint32_t a3,
                                         uint32_t b0, uint32_t b1) {
    asm volatile(
        "mma.sync.aligned.m16n8k16.row.col.f32.bf16.bf16.f32 "
        "{%0,%1,%2,%3}, {%4,%5,%6,%7}, {%8,%9}, {%0,%1,%2,%3};"
        : "+f"(c0), "+f"(c1), "+f"(c2), "+f"(c3)
        : "r"(a0), "r"(a1), "r"(a2), "r"(a3), "r"(b0), "r"(b1));
}

__device__ __forceinline__ void cp_async16(uint32_t sdst, const void* gsrc) {
    asm volatile(
        "{ .reg .u64 g; cvta.to.global.u64 g, %1; "
        "cp.async.cg.shared.global [%0], [g], 16; }"
        :: "r"(sdst), "l"(gsrc) : "memory");
}
#define CP_COMMIT() asm volatile("cp.async.commit_group;" ::: "memory")
#define CP_WAIT0()  asm volatile("cp.async.wait_group 0;" ::: "memory")

// ---------------- K1: prep W (bf16 copy + ||e||^2) ----------------
__global__ __launch_bounds__(256) void k_prep(const float* __restrict__ W) {
    int lane = threadIdx.x & 31;
    int wr = blockIdx.x * 8 + (threadIdx.x >> 5);
    const float4* p = (const float4*)(W + (size_t)wr * DIM);
    float4 a = p[2 * lane], b = p[2 * lane + 1];
    ((uint4*)g_Wb)[(size_t)wr * 32 + lane] = pack8(a, b);
    double s = (double)a.x * a.x + (double)a.y * a.y + (double)a.z * a.z + (double)a.w * a.w
             + (double)b.x * b.x + (double)b.y * b.y + (double)b.z * b.z + (double)b.w * b.w;
    #pragma unroll
    for (int o = 16; o; o >>= 1) s += __shfl_xor_sync(0xffffffffu, s, o);
    if (lane == 0) g_se[wr] = (float)s;
}

// ---------------- K1b: zero hist + mse (idempotent; also launch-slot padding) ----
__global__ __launch_bounds__(256) void k_hist0() {
    int gid = blockIdx.x * 256 + threadIdx.x;
    if (gid < NEMB) g_hist[gid] = 0;
    if (gid == 0) g_mse = 0.0;
}

// ---------------- K2: pipelined bf16 mma.sync GEMM + fused top-6 + enc zero ------
// 256 CTAs x 512 threads. Per CTA: 128 token rows; 32 chunks of 128 codes; K=256.
// 16 warps: warp tile 32x32 (mh=wid>>2 row band, nq=wid&3 col quarter).
// smem: A (128 x 528B), B0/B1 double buffer; D reuses the consumed B buffer.
#define ROWB 528
#define AOFF 0
#define B0OFF 67584
#define B1OFF 135168
#define SMEM_TOTAL 202752

__global__ __launch_bounds__(512, 1) void k_gemm(const float* __restrict__ X,
                                                 float* __restrict__ enc) {
    extern __shared__ char smem[];
    uint32_t sb = smem_u32(smem);
    const int tid = threadIdx.x, lane = tid & 31, wid = tid >> 5;
    const int mh = wid >> 2;          // 0..3 : 32-row band
    const int nq = wid & 3;           // 0..3 : 32-col quarter

    const char* wb = (const char*)g_Wb;
    // Preload B chunk 0
    #pragma unroll
    for (int i = 0; i < 8; i++) {
        int t = tid + i * 512;
        int r = t >> 5, c16 = t & 31;
        cp_async16(sb + B0OFF + r * ROWB + c16 * 16, wb + (size_t)r * 512 + c16 * 16);
    }
    CP_COMMIT();

    const int row0 = blockIdx.x * 128;
    // Load + convert A tile (128 rows x 256 f32 -> bf16, padded rows)
    #pragma unroll
    for (int i = 0; i < 8; i++) {
        int t = tid + i * 512;
        int r = t >> 5, k8 = t & 31;
        const float4* p = (const float4*)(X + (size_t)(row0 + r) * DIM + k8 * 8);
        *(uint4*)(smem + AOFF + r * ROWB + k8 * 16) = pack8(p[0], p[1]);
    }

    // ldmatrix lane addressing
    const int ag = lane >> 3;
    const int a_r = (lane & 7) + (ag & 1) * 8;
    const int a_k = (ag >> 1) * 8;
    const int b_n = (lane & 7) + (ag >> 1) * 8;
    const int b_k = (ag & 1) * 8;

    // scan ownership: thread owns quarter-row (srow, cols q4*32..+31)
    const int srow = tid >> 2, q4 = tid & 3;

    float tv[NCAND]; int tj[NCAND];
    #pragma unroll
    for (int s = 0; s < NCAND; s++) { tv[s] = -3.4e38f; tj[s] = 0; }
    float thr = -3.4e38f; int slot = 0;

    for (int c = 0; c < 32; c++) {
        const uint32_t buf = (c & 1) ? B1OFF : B0OFF;
        const uint32_t nbuf = (c & 1) ? B0OFF : B1OFF;

        CP_WAIT0();
        __syncthreads();          // chunk c's B visible; chunk c-1 scan complete

        if (c + 1 < 32) {
            #pragma unroll
            for (int i = 0; i < 8; i++) {
                int t = tid + i * 512;
                int r = t >> 5, c16 = t & 31;
                cp_async16(sb + nbuf + r * ROWB + c16 * 16,
                           wb + ((size_t)(c + 1) * 128 + r) * 512 + c16 * 16);
            }
            CP_COMMIT();
        }

        float acc[2][4][4];
        #pragma unroll
        for (int mt = 0; mt < 2; mt++)
            #pragma unroll
            for (int nt = 0; nt < 4; nt++)
                #pragma unroll
                for (int q = 0; q < 4; q++) acc[mt][nt][q] = 0.0f;

        #pragma unroll
        for (int kk = 0; kk < 16; kk++) {
            const int k0 = kk * 16;
            uint32_t af[2][4];
            #pragma unroll
            for (int mt = 0; mt < 2; mt++) {
                uint32_t addr = sb + AOFF + (mh * 32 + mt * 16 + a_r) * ROWB + (k0 + a_k) * 2;
                ldsm_x4(af[mt][0], af[mt][1], af[mt][2], af[mt][3], addr);
            }
            uint32_t bf[2][4];
            #pragma unroll
            for (int nt2 = 0; nt2 < 2; nt2++) {
                uint32_t addr = sb + buf + (nq * 32 + nt2 * 16 + b_n) * ROWB + (k0 + b_k) * 2;
                ldsm_x4(bf[nt2][0], bf[nt2][1], bf[nt2][2], bf[nt2][3], addr);
            }
            #pragma unroll
            for (int mt = 0; mt < 2; mt++)
                #pragma unroll
                for (int nt = 0; nt < 4; nt++) {
                    uint32_t b0 = bf[nt >> 1][(nt & 1) * 2];
                    uint32_t b1 = bf[nt >> 1][(nt & 1) * 2 + 1];
                    mma16816(acc[mt][nt][0], acc[mt][nt][1], acc[mt][nt][2], acc[mt][nt][3],
                             af[mt][0], af[mt][1], af[mt][2], af[mt][3], b0, b1);
                }
        }
        __syncthreads();          // all warps done reading buf; overwrite with D

        #pragma unroll
        for (int mt = 0; mt < 2; mt++) {
            int r = mh * 32 + mt * 16 + (lane >> 2);
            #pragma unroll
            for (int nt = 0; nt < 4; nt++) {
                int cb = nq * 32 + nt * 8 + 2 * (lane & 3);
                *(float2*)(smem + buf + r * ROWB + cb * 4) =
                    make_float2(acc[mt][nt][0], acc[mt][nt][1]);
                *(float2*)(smem + buf + (r + 8) * ROWB + cb * 4) =
                    make_float2(acc[mt][nt][2], acc[mt][nt][3]);
            }
        }
        __syncthreads();

        // zero the encodings slice for this (CTA rows, chunk cols): coalesced u32
        {
            float* ebase = enc + (size_t)row0 * NEMB + c * 128;
            #pragma unroll
            for (int i = 0; i < 32; i++) {
                int n = i * 512 + tid;          // 0..16383
                ebase[(size_t)(n >> 7) * NEMB + (n & 127)] = 0.0f;
            }
        }

        // per-quarter-row top-6 scan (private list, merged after chunk loop)
        {
            const float4* drow = (const float4*)(smem + buf + srow * ROWB + q4 * 128);
            int jb = c * 128 + q4 * 32;
            #pragma unroll
            for (int q = 0; q < 8; q++) {
                float4 v4 = drow[q];
                #pragma unroll
                for (int e = 0; e < 4; e++) {
                    float v = (e == 0) ? v4.x : (e == 1) ? v4.y : (e == 2) ? v4.z : v4.w;
                    if (v > thr) {
                        int j = jb + q * 4 + e;
                        #pragma unroll
                        for (int s = 0; s < NCAND; s++)
                            if (s == slot) { tv[s] = v; tj[s] = j; }
                        thr = tv[0]; slot = 0;
                        #pragma unroll
                        for (int s = 1; s < NCAND; s++)
                            if (tv[s] < thr) { thr = tv[s]; slot = s; }
                    }
                }
            }
        }
        // next iteration's CP_WAIT0+__syncthreads fences this scan before refill
    }

    // merge the 4 quarter-row lists (lanes tid^1, tid^2 are in the same warp)
    #pragma unroll
    for (int off = 1; off <= 2; off <<= 1) {
        float sv[NCAND]; int sj[NCAND];
        #pragma unroll
        for (int s = 0; s < NCAND; s++) { sv[s] = tv[s]; sj[s] = tj[s]; }
        #pragma unroll
        for (int s = 0; s < NCAND; s++) {
            float ov = __shfl_xor_sync(0xffffffffu, sv[s], off);
            int   oj = __shfl_xor_sync(0xffffffffu, sj[s], off);
            if (ov > thr) {
                #pragma unroll
                for (int t2 = 0; t2 < NCAND; t2++)
                    if (t2 == slot) { tv[t2] = ov; tj[t2] = oj; }
                thr = tv[0]; slot = 0;
                #pragma unroll
                for (int t2 = 1; t2 < NCAND; t2++)
                    if (tv[t2] < thr) { thr = tv[t2]; slot = t2; }
            }
        }
    }
    if (q4 == 0) {
        int row = row0 + srow;
        #pragma unroll
        for (int s = 0; s < NCAND; s++) g_cand[row * NCAND + s] = tj[s];
    }
}

// ---------------- K3: exact refine + quantized_st + losses + scatter -------------
// One warp per row; 8 rows per block. All 6 candidate dots batched (ILP), then one
// interleaved 7-way shuffle reduction.
__global__ __launch_bounds__(256) void k_refine(const float* __restrict__ X,
                                                const float* __restrict__ W,
                                                float* __restrict__ out) {
    __shared__ double sred[8];
    int lane = threadIdx.x & 31;
    int wip = threadIdx.x >> 5;
    int row = blockIdx.x * 8 + wip;
    const float4* xr = (const float4*)(X + (size_t)row * DIM);
    float4 xa = xr[2 * lane], xb = xr[2 * lane + 1];

    int jx[NCAND];
    #pragma unroll
    for (int s = 0; s < NCAND; s++) jx[s] = g_cand[row * NCAND + s];

    double m[NCAND + 1];
    m[NCAND] = (double)xa.x * xa.x + (double)xa.y * xa.y + (double)xa.z * xa.z + (double)xa.w * xa.w
             + (double)xb.x * xb.x + (double)xb.y * xb.y + (double)xb.z * xb.z + (double)xb.w * xb.w;
    #pragma unroll
    for (int s = 0; s < NCAND; s++) {
        const float4* wr = (const float4*)(W + (size_t)jx[s] * DIM);
        float4 wa = wr[2 * lane], wv = wr[2 * lane + 1];
        m[s] = (double)xa.x * wa.x + (double)xa.y * wa.y + (double)xa.z * wa.z + (double)xa.w * wa.w
             + (double)xb.x * wv.x + (double)xb.y * wv.y + (double)xb.z * wv.z + (double)xb.w * wv.w;
    }
    #pragma unroll
    for (int o = 16; o; o >>= 1) {
        #pragma unroll
        for (int s = 0; s < NCAND + 1; s++)
            m[s] += __shfl_xor_sync(0xffffffffu, m[s], o);
    }
    float sxf = (float)m[NCAND];

    float bd = 3.4e38f; int bj = 1 << 30;
    #pragma unroll
    for (int s = 0; s < NCAND; s++) {
        float mf = (float)m[s];                     // ~= reference's fp32 matmul entry
        float t1 = __fadd_rn(sxf, g_se[jx[s]]);     // fl(s_x + s_e[j])
        float d  = __fsub_rn(t1, 2.0f * mf);        // fl(t1 - 2m)  (x2 exact)
        if (d < bd || (d == bd && jx[s] < bj)) { bd = d; bj = jx[s]; }
    }

    // winner row reload (L2-hot) -> quantized_st + diff partials
    const float4* wr = (const float4*)(W + (size_t)bj * DIM);
    float4 wa = wr[2 * lane], wv = wr[2 * lane + 1];
    float d0 = __fsub_rn(wa.x, xa.x), d1 = __fsub_rn(wa.y, xa.y);
    float d2 = __fsub_rn(wa.z, xa.z), d3 = __fsub_rn(wa.w, xa.w);
    float d4 = __fsub_rn(wv.x, xb.x), d5 = __fsub_rn(wv.y, xb.y);
    float d6 = __fsub_rn(wv.z, xb.z), d7 = __fsub_rn(wv.w, xb.w);
    float4 qa, qb;
    qa.x = __fadd_rn(xa.x, d0); qa.y = __fadd_rn(xa.y, d1);
    qa.z = __fadd_rn(xa.z, d2); qa.w = __fadd_rn(xa.w, d3);
    qb.x = __fadd_rn(xb.x, d4); qb.y = __fadd_rn(xb.y, d5);
    qb.z = __fadd_rn(xb.z, d6); qb.w = __fadd_rn(xb.w, d7);
    float4* oq = (float4*)(out + Q_OFF + (size_t)row * DIM);
    oq[2 * lane] = qa; oq[2 * lane + 1] = qb;

    double ds = (double)d0 * d0 + (double)d1 * d1 + (double)d2 * d2 + (double)d3 * d3
              + (double)d4 * d4 + (double)d5 * d5 + (double)d6 * d6 + (double)d7 * d7;
    #pragma unroll
    for (int o = 16; o; o >>= 1) ds += __shfl_xor_sync(0xffffffffu, ds, o);
    if (lane == 0) {
        sred[wip] = ds;
        g_idx[row] = bj;
        out[IDX_OFF + row] = (float)bj;
        out[ENC_OFF + (size_t)row * NEMB + bj] = 1.0f;   // scatter one-hot
        atomicAdd(&g_hist[bj], 1);
    }
    __syncthreads();
    if (threadIdx.x == 0) {
        double t = 0.0;
        #pragma unroll
        for (int i = 0; i < 8; i++) t += sred[i];
        atomicAdd(&g_mse, t);
    }
}

// ---------------- K5: loss + perplexity ----------------
__global__ __launch_bounds__(1024) void k_final(float* __restrict__ out) {
    __shared__ double sB[1024];
    int t = threadIdx.x;
    double b = 0.0;
    for (int i = t; i < 4096; i += 1024) {
        float p = (float)g_hist[i] / 32768.0f;
        b += (double)(p * logf(p + 1e-10f));
    }
    sB[t] = b; __syncthreads();
    for (int o = 512; o; o >>= 1) {
        if (t < o) sB[t] += sB[t + o];
        __syncthreads();
    }
    if (t == 0) {
        double mse = g_mse / 8388608.0;
        float c = (float)mse;
        out[LOSS_OFF] = __fadd_rn(c, 0.25f * c);   // codebook + 0.25*commitment (equal values)
        out[PERP_OFF] = expf(-(float)sB[0]);
    }
}

// ---------------- launch ----------------
extern "C" void kernel_launch(void* const* d_in, const int* in_sizes, int n_in,
                              void* d_out, int out_size) {
    const float* X = (const float*)d_in[0];
    const float* W = (const float*)d_in[1];
    float* out = (float*)d_out;

    cudaFuncSetAttribute(k_gemm, cudaFuncAttributeMaxDynamicSharedMemorySize, SMEM_TOTAL);

    k_prep<<<512, 256>>>(W);                             // launch 1
    k_hist0<<<16, 256>>>();                              // 2 (idempotent padding)
    k_hist0<<<16, 256>>>();                              // 3
    k_hist0<<<16, 256>>>();                              // 4
    k_gemm<<<256, 512, SMEM_TOTAL>>>(X, out + ENC_OFF);  // 5 <- ncu slot
    k_refine<<<4096, 256>>>(X, W, out);                  // 6
    k_final<<<1, 1024>>>(out);                           // 7
}